// round 16
// baseline (speedup 1.0000x reference)
#include <cuda_runtime.h>
#include <cuda_bf16.h>

#define NCLS   1000
#define NCLS4  250          // NCLS / 4 float4 per row

// Scratch (no device allocation allowed -> __device__ globals)
// Fixed-point Q32 accumulators: integer REDs commute -> bit-deterministic.
__device__ unsigned long long g_lsum = 0;   // sum(loss) * 2^32
__device__ unsigned int       g_cnt  = 0;   // valid-token count
__device__ unsigned int       g_ctr  = 0;   // finished-warp ticket

__device__ __forceinline__ void red_add_u64(unsigned long long* p, unsigned long long v)
{
    asm volatile("red.relaxed.gpu.global.add.u64 [%0], %1;" :: "l"(p), "l"(v) : "memory");
}
__device__ __forceinline__ void red_add_u32(unsigned int* p, unsigned int v)
{
    asm volatile("red.relaxed.gpu.global.add.u32 [%0], %1;" :: "l"(p), "r"(v) : "memory");
}
// acq_rel RMW on the shared ticket: releases this warp's prior REDs and,
// for the last warp, acquires every earlier warp's released REDs.
__device__ __forceinline__ unsigned int ticket_acq_rel(unsigned int* p)
{
    unsigned int old;
    asm volatile("atom.acq_rel.gpu.global.add.u32 %0, [%1], 1;"
                 : "=r"(old) : "l"(p) : "memory");
    return old;
}
__device__ __forceinline__ unsigned long long ld_acq_u64(const unsigned long long* p)
{
    unsigned long long v;
    asm volatile("ld.acquire.gpu.global.u64 %0, [%1];" : "=l"(v) : "l"(p) : "memory");
    return v;
}
__device__ __forceinline__ unsigned int ld_acq_u32(const unsigned int* p)
{
    unsigned int v;
    asm volatile("ld.acquire.gpu.global.u32 %0, [%1];" : "=r"(v) : "l"(p) : "memory");
    return v;
}

// ---------------------------------------------------------------------------
// Single fused kernel, 1 token/warp, grid 4096, WARP-AUTONOMOUS epilogue:
// no __syncthreads, no shared memory, no inter-warp coupling. Each warp's
// lane 0 fires 2 fire-and-forget REDs + 1 ticket and exits; the globally
// last warp finalizes the scalar and resets state for the next graph replay.
// ---------------------------------------------------------------------------
__global__ __launch_bounds__(256) void hll_fused(
    const float* __restrict__ inputs,
    const int*   __restrict__ target,   // int32 (JAX downcasts int64 w/o x64)
    float* __restrict__ out,
    int N, int nwarp)
{
    const int lane = threadIdx.x & 31;
    const int n = (blockIdx.x << 3) + (threadIdx.x >> 5);

    float lsum = 0.f;
    bool  valid = false;

    if (n < N) {
        const int ti = target[n];
        valid = (ti != -100);
        const int t   = valid ? ti : 0;
        const int lo1 = (t / 10)  * 10;         // start of 10-block
        const int f0  = ((t / 100) * 100) >> 2; // first float4 of 100-block

        const float*  __restrict__ rowf = inputs + (size_t)n * NCLS;
        const float4* __restrict__ row  = reinterpret_cast<const float4*>(rowf);

        // ---- Streaming pass: s3 (all) + s2 (100-block, float4-aligned) ----
        float a0 = 0.f, a1 = 0.f, a2 = 0.f, a3 = 0.f;
        float s2 = 0.f;
        #pragma unroll
        for (int it = 0; it < 8; ++it) {
            const int idx = lane + (it << 5);
            if (idx < NCLS4) {
                const float4 v = row[idx];
                a0 += v.x; a1 += v.y; a2 += v.z; a3 += v.w;
                const float q = (v.x + v.y) + (v.z + v.w);
                if ((unsigned)(idx - f0) < 25u) s2 += q;
            }
        }
        float s3 = (a0 + a1) + (a2 + a3);

        // ---- Tiny re-read: 10-float s1 strip; s0 via shuffle from it ----
        const float s1v = (lane < 10) ? rowf[lo1 + lane] : 0.f;
        const float s0  = __shfl_sync(0xffffffffu, s1v, t - lo1);
        float s1 = s1v;

        // ---- Warp butterfly reduce s1,s2,s3 ----
        #pragma unroll
        for (int off = 16; off; off >>= 1) {
            s1 += __shfl_xor_sync(0xffffffffu, s1, off);
            s2 += __shfl_xor_sync(0xffffffffu, s2, off);
            s3 += __shfl_xor_sync(0xffffffffu, s3, off);
        }

        if (lane == 0 && valid) {
            const float u0 = (s0 != 0.f) ? -logf(s0 / s1) : 0.f;
            const float u1 = (s1 != 0.f) ? -logf(s1 / s2) : 0.f;
            const float u2 = (s2 != 0.f) ? -logf(s2 / s3) : 0.f;
            lsum = u0 + 0.60653065971263342f * u1   // exp(-0.5)
                      + 0.36787944117144233f * u2;  // exp(-1.0)
        }
    }

    // ---- Warp-autonomous epilogue (lane 0 only; no barrier) ----
    if (lane == 0) {
        if (valid) {
            // Exact: per-token loss has a 24-bit mantissa; |loss|*2^32 < 2^53.
            const unsigned long long fx =
                (unsigned long long)__double2ll_rn((double)lsum * 4294967296.0);
            red_add_u64(&g_lsum, fx);     // fire-and-forget
            red_add_u32(&g_cnt, 1u);      // fire-and-forget
        }
        const unsigned int ticket = ticket_acq_rel(&g_ctr);
        if (ticket == (unsigned)(nwarp - 1)) {
            // Globally last warp: all earlier REDs were released through the
            // ticket chain -> visible now. Finalize + reset for next replay.
            const unsigned long long ls = ld_acq_u64(&g_lsum);
            const unsigned int       cn = ld_acq_u32(&g_cnt);
            const double Lsum = (double)(long long)ls * (1.0 / 4294967296.0);
            const double cnt  = (cn > 0u) ? (double)cn : 1.0;
            out[0] = (float)(Lsum / cnt);
            g_lsum = 0ull;
            g_cnt  = 0u;
            g_ctr  = 0u;
        }
    }
}

// ---------------------------------------------------------------------------
// Inputs (metadata order): inputs f32 [N,1000], target i32 [N],
//                          onehot_num, onehot_den, weights (unused)
// ---------------------------------------------------------------------------
extern "C" void kernel_launch(void* const* d_in, const int* in_sizes, int n_in,
                              void* d_out, int out_size)
{
    const float* inputs = (const float*)d_in[0];
    const int*   target = (const int*)d_in[1];
    float*       out    = (float*)d_out;

    const int N = in_sizes[1];
    const int nblk = (N + 7) / 8;            // 4096 for N=32768 (1 tok/warp)

    hll_fused<<<nblk, 256>>>(inputs, target, out, N, nblk * 8);
}

// round 17
// speedup vs baseline: 1.1115x; 1.1115x over previous
#include <cuda_runtime.h>
#include <cuda_bf16.h>

#define NCLS   1000
#define NCLS4  250          // NCLS / 4 float4 per row
#define NSLOT  64           // distributed accumulator slots

// Scratch (no device allocation allowed -> __device__ globals)
// Fixed-point Q32 slot accumulators: integer REDs commute -> bit-deterministic.
__device__ unsigned long long g_lsum[NSLOT];   // sum(loss)*2^32, slotted
__device__ unsigned int       g_cnt [NSLOT];   // valid-token count, slotted
__device__ unsigned int       g_ctr = 0;       // finished-warp counter

__device__ __forceinline__ void red_add_u64(unsigned long long* p, unsigned long long v)
{
    asm volatile("red.relaxed.gpu.global.add.u64 [%0], %1;" :: "l"(p), "l"(v) : "memory");
}
__device__ __forceinline__ void red_add_u32(unsigned int* p, unsigned int v)
{
    asm volatile("red.relaxed.gpu.global.add.u32 [%0], %1;" :: "l"(p), "r"(v) : "memory");
}
// Fire-and-forget RELEASE increment: no return value, no producer wait.
__device__ __forceinline__ void red_inc_release(unsigned int* p)
{
    asm volatile("red.release.gpu.global.add.u32 [%0], 1;" :: "l"(p) : "memory");
}
__device__ __forceinline__ unsigned int ld_acq_u32(const unsigned int* p)
{
    unsigned int v;
    asm volatile("ld.acquire.gpu.global.u32 %0, [%1];" : "=r"(v) : "l"(p) : "memory");
    return v;
}

// ---------------------------------------------------------------------------
// Single kernel, grid nblk+1:
//   block 0            = finalizer (spins on counter; reduces slots; resets)
//   blocks 1..nblk     = producers, 1 token/warp, WARP-AUTONOMOUS epilogue:
//                        no __syncthreads, no smem, no returning atomics.
// ---------------------------------------------------------------------------
__global__ __launch_bounds__(256) void hll_fused(
    const float* __restrict__ inputs,
    const int*   __restrict__ target,   // int32 (JAX downcasts int64 w/o x64)
    float* __restrict__ out,
    int N, int nwarp)
{
    const int lane = threadIdx.x & 31;

    // ================= Finalizer block =================
    if (blockIdx.x == 0) {
        if (threadIdx.x >= 32) return;   // one warp only
        // Spin until all producer warps have released their REDs.
        while (ld_acq_u32(&g_ctr) < (unsigned)nwarp) __nanosleep(128);

        // Fixed-order slot reduction (2 slots per lane) -> deterministic.
        unsigned long long l = g_lsum[lane] + g_lsum[lane + 32];
        unsigned int       c = g_cnt [lane] + g_cnt [lane + 32];
        #pragma unroll
        for (int off = 16; off; off >>= 1) {
            l += __shfl_xor_sync(0xffffffffu, l, off);
            c += __shfl_xor_sync(0xffffffffu, c, off);
        }
        if (lane == 0) {
            const double Lsum = (double)(long long)l * (1.0 / 4294967296.0);
            const double cnt  = (c > 0u) ? (double)c : 1.0;
            out[0] = (float)(Lsum / cnt);
            g_ctr = 0u;
        }
        // Reset slots for the next graph replay (visible at kernel end).
        g_lsum[lane]      = 0ull;  g_lsum[lane + 32] = 0ull;
        g_cnt [lane]      = 0u;    g_cnt [lane + 32] = 0u;
        return;
    }

    // ================= Producer blocks =================
    const int n = ((blockIdx.x - 1) << 3) + (threadIdx.x >> 5);

    float lsum = 0.f;
    bool  valid = false;

    if (n < N) {
        const int ti = target[n];
        valid = (ti != -100);
        const int t   = valid ? ti : 0;
        const int lo1 = (t / 10)  * 10;         // start of 10-block
        const int f0  = ((t / 100) * 100) >> 2; // first float4 of 100-block

        const float*  __restrict__ rowf = inputs + (size_t)n * NCLS;
        const float4* __restrict__ row  = reinterpret_cast<const float4*>(rowf);

        // ---- Streaming pass: s3 (all) + s2 (100-block, float4-aligned) ----
        float a0 = 0.f, a1 = 0.f, a2 = 0.f, a3 = 0.f;
        float s2 = 0.f;
        #pragma unroll
        for (int it = 0; it < 8; ++it) {
            const int idx = lane + (it << 5);
            if (idx < NCLS4) {
                const float4 v = row[idx];
                a0 += v.x; a1 += v.y; a2 += v.z; a3 += v.w;
                const float q = (v.x + v.y) + (v.z + v.w);
                if ((unsigned)(idx - f0) < 25u) s2 += q;
            }
        }
        float s3 = (a0 + a1) + (a2 + a3);

        // ---- Tiny re-read: 10-float s1 strip; s0 via shuffle from it ----
        const float s1v = (lane < 10) ? rowf[lo1 + lane] : 0.f;
        const float s0  = __shfl_sync(0xffffffffu, s1v, t - lo1);
        float s1 = s1v;

        // ---- Warp butterfly reduce s1,s2,s3 ----
        #pragma unroll
        for (int off = 16; off; off >>= 1) {
            s1 += __shfl_xor_sync(0xffffffffu, s1, off);
            s2 += __shfl_xor_sync(0xffffffffu, s2, off);
            s3 += __shfl_xor_sync(0xffffffffu, s3, off);
        }

        if (lane == 0 && valid) {
            const float u0 = (s0 != 0.f) ? -logf(s0 / s1) : 0.f;
            const float u1 = (s1 != 0.f) ? -logf(s1 / s2) : 0.f;
            const float u2 = (s2 != 0.f) ? -logf(s2 / s3) : 0.f;
            lsum = u0 + 0.60653065971263342f * u1   // exp(-0.5)
                      + 0.36787944117144233f * u2;  // exp(-1.0)
        }
    }

    // ---- Warp-autonomous epilogue: fire-and-forget only, never waits ----
    if (lane == 0) {
        if (valid) {
            // Exact: per-token loss has a 24-bit mantissa; |loss|*2^32 < 2^53.
            const unsigned long long fx =
                (unsigned long long)__double2ll_rn((double)lsum * 4294967296.0);
            const int slot = n & (NSLOT - 1);
            red_add_u64(&g_lsum[slot], fx);
            red_add_u32(&g_cnt [slot], 1u);
        }
        red_inc_release(&g_ctr);   // releases the REDs above; no return
    }
}

// ---------------------------------------------------------------------------
// Inputs (metadata order): inputs f32 [N,1000], target i32 [N],
//                          onehot_num, onehot_den, weights (unused)
// ---------------------------------------------------------------------------
extern "C" void kernel_launch(void* const* d_in, const int* in_sizes, int n_in,
                              void* d_out, int out_size)
{
    const float* inputs = (const float*)d_in[0];
    const int*   target = (const int*)d_in[1];
    float*       out    = (float*)d_out;

    const int N = in_sizes[1];
    const int nblk = (N + 7) / 8;            // 4096 producer blocks
    const int nwarp = nblk * 8;              // every producer warp tickets

    hll_fused<<<nblk + 1, 256>>>(inputs, target, out, N, nwarp);
}